// round 8
// baseline (speedup 1.0000x reference)
#include <cuda_runtime.h>
#include <cuda_bf16.h>
#include <cstdint>

// ---------------------------------------------------------------------------
// Problem constants
// ---------------------------------------------------------------------------
#define BB      2
#define LL      4096
#define DMODEL  768
#define DSTATE  16
#define DCONV   4
#define DINNER  1536
#define DTRANK  48
#define NTOT    (BB*LL)              // 8192
#define EPROJ   (DTRANK + 2*DSTATE)  // 80

// GEMM smem geometry
#define PITCH_A   48                  // bytes/row, A & B(TB=true) smem (16 bf16 + pad)
#define PITCH_BF  272                 // bytes/row, B(TB=false) smem (128 bf16 + pad)
#define SLOT_A    (128*PITCH_A)       // 6144 per plane
#define SLOT_BF   (16*PITCH_BF)       // 4352 per plane
// per-template stage size: A planes + B planes
#define STAGE_T   (2*SLOT_A + 2*SLOT_A)    // 24576 (TB=true)
#define STAGE_F   (2*SLOT_A + 2*SLOT_BF)   // 20992 (TB=false)
#define SMEM_T    (3*STAGE_T)              // 73728
#define SMEM_F    (3*STAGE_F)              // 62976

// ---------------------------------------------------------------------------
// Scratch — GEMM operands as hi/lo bf16 planes; scan-facing data packed
// ---------------------------------------------------------------------------
__device__ __nv_bfloat16 g_hidh [NTOT*DMODEL],     g_hidl [NTOT*DMODEL];
__device__ __nv_bfloat16 g_inph [2*DINNER*DMODEL], g_inpl [2*DINNER*DMODEL];
__device__ __nv_bfloat16 g_outph[DMODEL*DINNER],   g_outpl[DMODEL*DINNER];
__device__ __nv_bfloat16 g_xpah [EPROJ*DINNER],    g_xpal [EPROJ*DINNER];
__device__ __nv_bfloat16 g_xpbh [EPROJ*DINNER],    g_xpbl [EPROJ*DINNER];
__device__ __nv_bfloat16 g_dtpah[DINNER*DTRANK],   g_dtpal[DINNER*DTRANK];
__device__ __nv_bfloat16 g_dtpbh[DINNER*DTRANK],   g_dtpbl[DINNER*DTRANK];

__device__ float         g_xz   [2*DINNER*NTOT];   // in_proj out fp32 (x | z)
__device__ __nv_bfloat16 g_xcah [DINNER*NTOT], g_xcal[DINNER*NTOT];  // GEMM3 B
__device__ __nv_bfloat16 g_xcbh [DINNER*NTOT], g_xcbl[DINNER*NTOT];
__device__ uint32_t      g_xca_p[DINNER*NTOT];     // scan u, packed lo<<16|hi
__device__ uint32_t      g_xcb_p[DINNER*NTOT];
__device__ __nv_bfloat16 g_dtinah[DTRANK*NTOT], g_dtinal[DTRANK*NTOT];
__device__ __nv_bfloat16 g_dtinbh[DTRANK*NTOT], g_dtinbl[DTRANK*NTOT];
__device__ float         g_bca  [2*DSTATE*NTOT];   // interleaved {B,C} fp32
__device__ float         g_bcb  [2*DSTATE*NTOT];
__device__ uint32_t      g_da_p [DINNER*NTOT];     // delta packed (scan only)
__device__ uint32_t      g_db_p [DINNER*NTOT];
__device__ float         g_ya   [DINNER*NTOT];
__device__ float         g_yb   [DINNER*NTOT];
__device__ __nv_bfloat16 g_yph  [DINNER*NTOT], g_ypl[DINNER*NTOT];

// ---------------------------------------------------------------------------
// Helpers
// ---------------------------------------------------------------------------
__device__ __forceinline__ float softplus_f(float x) {
    return (x > 20.f) ? x : log1pf(__expf(x));
}
__device__ __forceinline__ float silu_f(float x) {
    return x / (1.f + __expf(-x));
}
__device__ __forceinline__ void split_hl(float x, __nv_bfloat16& h, __nv_bfloat16& l) {
    h = __float2bfloat16(x);
    l = __float2bfloat16(x - __bfloat162float(h));
}
__device__ __forceinline__ uint32_t bfpack(__nv_bfloat16 a, __nv_bfloat16 b) {
    return ((uint32_t)__bfloat16_as_ushort(b) << 16) | (uint32_t)__bfloat16_as_ushort(a);
}
__device__ __forceinline__ uint32_t pack_bf2(float x) {
    __nv_bfloat16 h, l;
    split_hl(x, h, l);
    return ((uint32_t)__bfloat16_as_ushort(l) << 16) | (uint32_t)__bfloat16_as_ushort(h);
}
__device__ __forceinline__ float unpack_bf2(uint32_t w) {
    return __bfloat162float(__ushort_as_bfloat16((unsigned short)(w & 0xffffu))) +
           __bfloat162float(__ushort_as_bfloat16((unsigned short)(w >> 16)));
}
__device__ __forceinline__ void mma_bf16(float c[4], const uint32_t a[4], const uint32_t b[2]) {
    asm volatile(
        "mma.sync.aligned.m16n8k16.row.col.f32.bf16.bf16.f32 "
        "{%0,%1,%2,%3}, {%4,%5,%6,%7}, {%8,%9}, {%0,%1,%2,%3};"
        : "+f"(c[0]), "+f"(c[1]), "+f"(c[2]), "+f"(c[3])
        : "r"(a[0]), "r"(a[1]), "r"(a[2]), "r"(a[3]), "r"(b[0]), "r"(b[1]));
}
__device__ __forceinline__ uint32_t smem_u32(const void* p) {
    uint32_t a;
    asm("{ .reg .u64 t; cvta.to.shared.u64 t, %1; cvt.u32.u64 %0, t; }"
        : "=r"(a) : "l"(p));
    return a;
}
__device__ __forceinline__ void ldsm_x4(uint32_t* r, uint32_t a) {
    asm volatile("ldmatrix.sync.aligned.m8n8.x4.shared.b16 {%0,%1,%2,%3}, [%4];"
                 : "=r"(r[0]), "=r"(r[1]), "=r"(r[2]), "=r"(r[3]) : "r"(a));
}
__device__ __forceinline__ void ldsm_x4_t(uint32_t* r, uint32_t a) {
    asm volatile("ldmatrix.sync.aligned.m8n8.x4.trans.shared.b16 {%0,%1,%2,%3}, [%4];"
                 : "=r"(r[0]), "=r"(r[1]), "=r"(r[2]), "=r"(r[3]) : "r"(a));
}
__device__ __forceinline__ void cp16(uint32_t dst, const void* src) {
    asm volatile("cp.async.ca.shared.global [%0], [%1], 16;" :: "r"(dst), "l"(src));
}
#define CP_COMMIT() asm volatile("cp.async.commit_group;" ::: "memory")
#define CP_WAIT1()  asm volatile("cp.async.wait_group 1;" ::: "memory")

// ---------------------------------------------------------------------------
// bf16 3-pass GEMM, cp.async + ldmatrix, hi/lo plane operands.
//   EPI 0: fp32 C (CT: C[n][m]).
//   EPI 1: softplus(acc+bias[m]) -> packed C2 (scan format).
//   EPI 2: rows<48 -> planes Ch/Cl ; rows 48..79 -> interleaved {B,C} fp32 C.
// 3-stage cp.async pipeline, per-template stage size, carveout raised host-side
// so 2 blocks/SM can be resident.
// ---------------------------------------------------------------------------
struct GArgs {
    const __nv_bfloat16 *Ah, *Al, *Bh, *Bl;
    float* C;
    uint32_t* C2;
    __nv_bfloat16 *Ch, *Cl;
    const float* bias;
};

template<int EPI, bool TB, bool CT>
__global__ __launch_bounds__(256, 2)
void gemm_cp(GArgs g0, GArgs g1, int M, int N, int K,
             int lda, int ldb, int ldc)
{
    constexpr int STAGE = TB ? STAGE_T : STAGE_F;
    extern __shared__ __align__(16) char smem[];
    const GArgs ga = blockIdx.z ? g1 : g0;

    const int tid  = threadIdx.x;
    const int w    = tid >> 5;
    const int wm   = w >> 2;
    const int wn   = w & 3;
    const int lane = tid & 31;
    const int gq   = lane >> 2;
    const int t    = lane & 3;
    const int l7   = lane & 7;
    const int mg   = lane >> 3;
    const int m0   = blockIdx.y * 128;
    const int n0   = blockIdx.x * 128;
    const uint32_t sbase = smem_u32(smem);

    const uint32_t aoff =
        (uint32_t)((wm*64 + l7 + ((mg & 1) << 3)) * PITCH_A + ((mg >> 1) << 4));
    uint32_t boff;
    if (!TB) boff = (uint32_t)((l7 + ((mg & 1) << 3)) * PITCH_BF
                               + (wn*32 + ((mg >> 1) << 3)) * 2);
    else     boff = (uint32_t)((wn*32 + l7 + ((mg >> 1) << 3)) * PITCH_A
                               + ((mg & 1) << 4));

    float acc[4][4][4];
#pragma unroll
    for (int i = 0; i < 4; ++i)
#pragma unroll
        for (int j = 0; j < 4; ++j)
#pragma unroll
            for (int c = 0; c < 4; ++c) acc[i][j][c] = 0.f;

    auto issue = [&](int st, int k0) {
        uint32_t sb = sbase + st*STAGE;
#pragma unroll
        for (int p = 0; p < 2; ++p) {
            int c = tid + p*256;
            int plane = c >> 8, row = (c >> 1) & 127, half = c & 1;
            int gm = m0 + row; if (gm > M-1) gm = M-1;
            const __nv_bfloat16* src =
                (plane ? ga.Al : ga.Ah) + (long)gm*lda + k0 + half*8;
            cp16(sb + plane*SLOT_A + row*PITCH_A + half*16, src);
        }
        uint32_t bb = sb + 2*SLOT_A;
        if (!TB) {
#pragma unroll
            for (int p = 0; p < 2; ++p) {
                int c = tid + p*256;
                int plane = c >> 8, row = (c >> 4) & 15, seg = c & 15;
                const __nv_bfloat16* src =
                    (plane ? ga.Bl : ga.Bh) + (long)(k0 + row)*ldb + n0 + seg*8;
                cp16(bb + plane*SLOT_BF + row*PITCH_BF + seg*16, src);
            }
        } else {
#pragma unroll
            for (int p = 0; p < 2; ++p) {
                int c = tid + p*256;
                int plane = c >> 8, row = (c >> 1) & 127, half = c & 1;
                const __nv_bfloat16* src =
                    (plane ? ga.Bl : ga.Bh) + (long)(n0 + row)*ldb + k0 + half*8;
                cp16(bb + plane*SLOT_A + row*PITCH_A + half*16, src);
            }
        }
    };

    const int iters = K / 16;
    issue(0, 0);  CP_COMMIT();
    issue(1, 16); CP_COMMIT();

    for (int it = 0; it < iters; ++it) {
        CP_WAIT1();
        __syncthreads();
        if (it + 2 < iters) issue((it + 2) % 3, (it + 2) * 16);
        CP_COMMIT();

        const uint32_t st = sbase + (it % 3)*STAGE;
        const uint32_t bb = st + 2*SLOT_A + boff;

        uint32_t bh[4][2], bl[4][2];
        if (!TB) {
            uint32_t r[4];
            ldsm_x4_t(r, bb);
            bh[0][0]=r[0]; bh[0][1]=r[1]; bh[1][0]=r[2]; bh[1][1]=r[3];
            ldsm_x4_t(r, bb + 32);
            bh[2][0]=r[0]; bh[2][1]=r[1]; bh[3][0]=r[2]; bh[3][1]=r[3];
            ldsm_x4_t(r, bb + SLOT_BF);
            bl[0][0]=r[0]; bl[0][1]=r[1]; bl[1][0]=r[2]; bl[1][1]=r[3];
            ldsm_x4_t(r, bb + SLOT_BF + 32);
            bl[2][0]=r[0]; bl[2][1]=r[1]; bl[3][0]=r[2]; bl[3][1]=r[3];
        } else {
            uint32_t r[4];
            ldsm_x4(r, bb);
            bh[0][0]=r[0]; bh[0][1]=r[1]; bh[1][0]=r[2]; bh[1][1]=r[3];
            ldsm_x4(r, bb + 16*PITCH_A);
            bh[2][0]=r[0]; bh[2][1]=r[1]; bh[3][0]=r[2]; bh[3][1]=r[3];
            ldsm_x4(r, bb + SLOT_A);
            bl[0][0]=r[0]; bl[0][1]=r[1]; bl[1][0]=r[2]; bl[1][1]=r[3];
            ldsm_x4(r, bb + SLOT_A + 16*PITCH_A);
            bl[2][0]=r[0]; bl[2][1]=r[1]; bl[3][0]=r[2]; bl[3][1]=r[3];
        }

#pragma unroll
        for (int mt = 0; mt < 4; ++mt) {
            uint32_t ah[4], al[4];
            ldsm_x4(ah, st + aoff + mt*16*PITCH_A);
            ldsm_x4(al, st + SLOT_A + aoff + mt*16*PITCH_A);
#pragma unroll
            for (int nt = 0; nt < 4; ++nt) mma_bf16(acc[mt][nt], ah, bh[nt]);
#pragma unroll
            for (int nt = 0; nt < 4; ++nt) mma_bf16(acc[mt][nt], ah, bl[nt]);
#pragma unroll
            for (int nt = 0; nt < 4; ++nt) mma_bf16(acc[mt][nt], al, bh[nt]);
        }
    }

    // ---- epilogue ----
#pragma unroll
    for (int mt = 0; mt < 4; ++mt) {
#pragma unroll
        for (int nt = 0; nt < 4; ++nt) {
            int gm = m0 + wm*64 + mt*16 + gq;
            int gn = n0 + wn*32 + nt*8 + 2*t;
            float c0 = acc[mt][nt][0], c1 = acc[mt][nt][1];
            float c2 = acc[mt][nt][2], c3 = acc[mt][nt][3];
            if (EPI == 0) {
                if (!CT) {
                    if (gm < M) {
                        ga.C[(long)gm*ldc + gn]     = c0;
                        ga.C[(long)gm*ldc + gn + 1] = c1;
                    }
                    if (gm + 8 < M) {
                        ga.C[(long)(gm+8)*ldc + gn]     = c2;
                        ga.C[(long)(gm+8)*ldc + gn + 1] = c3;
                    }
                } else {
                    if (gm < M) {
                        ga.C[(long)gn*ldc + gm]       = c0;
                        ga.C[(long)(gn+1)*ldc + gm]   = c1;
                    }
                    if (gm + 8 < M) {
                        ga.C[(long)gn*ldc + gm + 8]     = c2;
                        ga.C[(long)(gn+1)*ldc + gm + 8] = c3;
                    }
                }
            } else if (EPI == 1) {
                if (gm < M) {
                    float b0 = ga.bias[gm];
                    ga.C2[(long)gm*ldc + gn]     = pack_bf2(softplus_f(c0 + b0));
                    ga.C2[(long)gm*ldc + gn + 1] = pack_bf2(softplus_f(c1 + b0));
                }
                if (gm + 8 < M) {
                    float b1 = ga.bias[gm + 8];
                    ga.C2[(long)(gm+8)*ldc + gn]     = pack_bf2(softplus_f(c2 + b1));
                    ga.C2[(long)(gm+8)*ldc + gn + 1] = pack_bf2(softplus_f(c3 + b1));
                }
            } else { // EPI 2
                if (gm < DTRANK) {
                    __nv_bfloat16 h0,l0,h1,l1;
                    split_hl(c0,h0,l0); split_hl(c1,h1,l1);
                    *(uint32_t*)(ga.Ch + (long)gm*ldc + gn) = bfpack(h0,h1);
                    *(uint32_t*)(ga.Cl + (long)gm*ldc + gn) = bfpack(l0,l1);
                } else if (gm < EPROJ) {
                    int r = gm - DTRANK, s = r & 15, wch = r >> 4;
                    ga.C[(((long)gn*16 + s) << 1) + wch]       = c0;
                    ga.C[(((long)(gn+1)*16 + s) << 1) + wch]   = c1;
                }
                if (gm + 8 < DTRANK) {
                    __nv_bfloat16 h2,l2,h3,l3;
                    split_hl(c2,h2,l2); split_hl(c3,h3,l3);
                    *(uint32_t*)(ga.Ch + (long)(gm+8)*ldc + gn) = bfpack(h2,h3);
                    *(uint32_t*)(ga.Cl + (long)(gm+8)*ldc + gn) = bfpack(l2,l3);
                } else if (gm + 8 < EPROJ) {
                    int r = gm + 8 - DTRANK, s = r & 15, wch = r >> 4;
                    ga.C[(((long)gn*16 + s) << 1) + wch]       = c2;
                    ga.C[(((long)(gn+1)*16 + s) << 1) + wch]   = c3;
                }
            }
        }
    }
}

// ---------------------------------------------------------------------------
// Split fp32 -> hi/lo bf16 planes, 7 segments fused
// ---------------------------------------------------------------------------
struct Seg { const float* s; __nv_bfloat16 *h, *l; long c; };

__global__ void split_multi(Seg s0, Seg s1, Seg s2, Seg s3, Seg s4, Seg s5, Seg s6)
{
    long q = ((long)blockIdx.x * blockDim.x + threadIdx.x) * 4;
    Seg sg;
    if      (q < s0.c) sg = s0;
    else if ((q -= s0.c) < s1.c) sg = s1;
    else if ((q -= s1.c) < s2.c) sg = s2;
    else if ((q -= s2.c) < s3.c) sg = s3;
    else if ((q -= s3.c) < s4.c) sg = s4;
    else if ((q -= s4.c) < s5.c) sg = s5;
    else if ((q -= s5.c) < s6.c) sg = s6;
    else return;
    float4 v = *(const float4*)(sg.s + q);
    __nv_bfloat16 h0,l0,h1,l1,h2,l2,h3,l3;
    split_hl(v.x,h0,l0); split_hl(v.y,h1,l1);
    split_hl(v.z,h2,l2); split_hl(v.w,h3,l3);
    *(uint2*)(sg.h + q) = make_uint2(bfpack(h0,h1), bfpack(h2,h3));
    *(uint2*)(sg.l + q) = make_uint2(bfpack(l0,l1), bfpack(l2,l3));
}

// ---------------------------------------------------------------------------
// Fused depthwise conv(w=4)+SiLU, both branches.
// Writes planes (GEMM3 operand) AND packed (scan operand).
// ---------------------------------------------------------------------------
__global__ __launch_bounds__(256)
void conv_silu_both(const float* __restrict__ x,
                    const float* __restrict__ wa, const float* __restrict__ ba,
                    const float* __restrict__ wb, const float* __restrict__ bb,
                    __nv_bfloat16* __restrict__ oah, __nv_bfloat16* __restrict__ oal,
                    __nv_bfloat16* __restrict__ obh, __nv_bfloat16* __restrict__ obl,
                    uint32_t* __restrict__ oap, uint32_t* __restrict__ obp)
{
    long q = (long)blockIdx.x * blockDim.x + threadIdx.x;   // 4 l per thread
    const long PERD = NTOT/4;
    int d  = (int)(q / PERD);
    int n4 = (int)(q % PERD);
    int n  = n4 * 4;
    int b  = n / LL;
    int l0 = n % LL;

    const float* xr = x + (long)d*NTOT + (long)b*LL;
    float4 prev = (l0 >= 4)      ? *(const float4*)(xr + l0 - 4) : make_float4(0,0,0,0);
    float4 cur  =                  *(const float4*)(xr + l0);
    float4 next = (l0 + 4 < LL)  ? *(const float4*)(xr + l0 + 4) : make_float4(0,0,0,0);

    float xa[8] = {prev.x, prev.y, prev.z, prev.w, cur.x, cur.y, cur.z, cur.w};
    float xb[8] = {cur.x, cur.y, cur.z, cur.w, next.x, next.y, next.z, next.w};

    float wav[4], wbv[4];
#pragma unroll
    for (int k = 0; k < 4; ++k) { wav[k] = wa[d*4+k]; wbv[k] = wb[d*4+k]; }
    float bav = ba[d], bbv = bb[d];

    __nv_bfloat16 ah[4], al[4], bh[4], bl[4];
#pragma unroll
    for (int j = 0; j < 4; ++j) {
        float sa = bav, sb = bbv;
#pragma unroll
        for (int k = 0; k < 4; ++k) {
            sa = fmaf(wav[k], xa[j + 1 + k], sa);
            sb = fmaf(wbv[k], xb[j + 3 - k], sb);
        }
        split_hl(silu_f(sa), ah[j], al[j]);
        split_hl(silu_f(sb), bh[j], bl[j]);
    }
    long off = (long)d*NTOT + n;
    *(uint2*)(oah + off) = make_uint2(bfpack(ah[0],ah[1]), bfpack(ah[2],ah[3]));
    *(uint2*)(oal + off) = make_uint2(bfpack(al[0],al[1]), bfpack(al[2],al[3]));
    *(uint2*)(obh + off) = make_uint2(bfpack(bh[0],bh[1]), bfpack(bh[2],bh[3]));
    *(uint2*)(obl + off) = make_uint2(bfpack(bl[0],bl[1]), bfpack(bl[2],bl[3]));
    uint4 pa, pb;
    pa.x = bfpack(ah[0], al[0]); pa.y = bfpack(ah[1], al[1]);
    pa.z = bfpack(ah[2], al[2]); pa.w = bfpack(ah[3], al[3]);
    pb.x = bfpack(bh[0], bl[0]); pb.y = bfpack(bh[1], bl[1]);
    pb.z = bfpack(bh[2], bl[2]); pb.w = bfpack(bh[3], bl[3]);
    *(uint4*)(oap + off) = pa;
    *(uint4*)(obp + off) = pb;
}

// ---------------------------------------------------------------------------
// Selective scan, packed u/delta, depth-1 prefetch. One warp = two units
// (d, d+768), same (branch,b). bc: float2 {B,C} at [(b*LL+l)*16 + state].
// ---------------------------------------------------------------------------
struct ScanArgs {
    const uint32_t *u, *dl;
    const float *bc, *Al, *Dv;
    float* y;
};

__global__ __launch_bounds__(256)
void scan_both(ScanArgs sa, ScanArgs sb)
{
    const int lane   = threadIdx.x & 31;
    const int lane16 = lane & 15;
    const int hh     = lane >> 4;
    int warpId = blockIdx.x * (blockDim.x >> 5) + (threadIdx.x >> 5);

    const int branch = warpId / (BB * (DINNER/2));
    int rem = warpId % (BB * (DINNER/2));
    const int b  = rem / (DINNER/2);
    const int dp = rem % (DINNER/2);
    const int d  = dp + hh * (DINNER/2);

    const ScanArgs& A_ = branch ? sb : sa;
    const bool fwd = (branch == 0);

    long base = (long)d*NTOT + (long)b*LL;
    const uint32_t* uR = A_.u  + base;
    const uint32_t* dR = A_.dl + base;
    const float2* bcR = (const float2*)A_.bc + ((long)b*LL)*16 + lane16;
    float* yR = A_.y + base;

    float A  = -__expf(A_.Al[d*DSTATE + lane16]);
    float Dd = A_.Dv[d];
    float hS = 0.f;

    int l0 = fwd ? 0 : LL - 4;
    uint4  u4 = *(const uint4*)(uR + l0);
    uint4  d4 = *(const uint4*)(dR + l0);
    float2 s0 = bcR[(long)(l0+0)*16];
    float2 s1 = bcR[(long)(l0+1)*16];
    float2 s2 = bcR[(long)(l0+2)*16];
    float2 s3 = bcR[(long)(l0+3)*16];

    for (int q = 0; q < LL/4; ++q) {
        int l0n = fwd ? (q+1)*4 : (LL - 8 - q*4);
        uint4 u4n = make_uint4(0,0,0,0), d4n = make_uint4(0,0,0,0);
        float2 t0 = make_float2(0,0), t1 = t0, t2 = t0, t3 = t0;
        if (q + 1 < LL/4) {
            u4n = *(const uint4*)(uR + l0n);
            d4n = *(const uint4*)(dR + l0n);
            t0 = bcR[(long)(l0n+0)*16];
            t1 = bcR[(long)(l0n+1)*16];
            t2 = bcR[(long)(l0n+2)*16];
            t3 = bcR[(long)(l0n+3)*16];
        }
        float uu[4] = {unpack_bf2(u4.x), unpack_bf2(u4.y), unpack_bf2(u4.z), unpack_bf2(u4.w)};
        float dd[4] = {unpack_bf2(d4.x), unpack_bf2(d4.y), unpack_bf2(d4.z), unpack_bf2(d4.w)};
        float Bv[4] = {s0.x, s1.x, s2.x, s3.x};
        float Cv[4] = {s0.y, s1.y, s2.y, s3.y};
        float yout[4];
#pragma unroll
        for (int j = 0; j < 4; ++j) {
            int jj = fwd ? j : 3 - j;
            float ut = uu[jj];
            float dt = dd[jj];
            float dA = __expf(dt * A);
            hS = fmaf(dA, hS, dt * ut * Bv[jj]);
            float p = hS * Cv[jj];
            p += __shfl_xor_sync(0xffffffffu, p, 1);
            p += __shfl_xor_sync(0xffffffffu, p, 2);
            p += __shfl_xor_sync(0xffffffffu, p, 4);
            p += __shfl_xor_sync(0xffffffffu, p, 8);
            yout[jj] = fmaf(ut, Dd, p);
        }
        if (lane16 == 0)
            *(float4*)(yR + l0) = make_float4(yout[0], yout[1], yout[2], yout[3]);
        u4 = u4n; d4 = d4n;
        s0 = t0; s1 = t1; s2 = t2; s3 = t3; l0 = l0n;
    }
}

// ---------------------------------------------------------------------------
// Combine: y = (ya + yb) * silu(z) -> planes (GEMM7 operand)
// ---------------------------------------------------------------------------
__global__ void combine_kernel(const float* __restrict__ ya,
                               const float* __restrict__ yb,
                               const float* __restrict__ xz,
                               __nv_bfloat16* __restrict__ yh,
                               __nv_bfloat16* __restrict__ yl)
{
    long q = ((long)blockIdx.x * blockDim.x + threadIdx.x) * 4;
    if (q >= (long)DINNER*NTOT) return;
    float4 a = *(const float4*)(ya + q);
    float4 b = *(const float4*)(yb + q);
    float4 z = *(const float4*)(xz + (long)DINNER*NTOT + q);
    __nv_bfloat16 h0,l0,h1,l1,h2,l2,h3,l3;
    split_hl((a.x + b.x) * silu_f(z.x), h0, l0);
    split_hl((a.y + b.y) * silu_f(z.y), h1, l1);
    split_hl((a.z + b.z) * silu_f(z.z), h2, l2);
    split_hl((a.w + b.w) * silu_f(z.w), h3, l3);
    *(uint2*)(yh + q) = make_uint2(bfpack(h0,h1), bfpack(h2,h3));
    *(uint2*)(yl + q) = make_uint2(bfpack(l0,l1), bfpack(l2,l3));
}

// ---------------------------------------------------------------------------
// Host launcher
// ---------------------------------------------------------------------------
template<typename T>
static T* sym_addr(const void* sym) {
    void* p = nullptr;
    cudaGetSymbolAddress(&p, sym);
    return (T*)p;
}

template<typename K>
static void set_gemm_attrs(K k, int smem) {
    cudaFuncSetAttribute(k, cudaFuncAttributeMaxDynamicSharedMemorySize, smem);
    cudaFuncSetAttribute(k, cudaFuncAttributePreferredSharedMemoryCarveout, 100);
}

extern "C" void kernel_launch(void* const* d_in, const int* in_sizes, int n_in,
                              void* d_out, int out_size)
{
    const float* hidden    = (const float*)d_in[0];
    const float* in_proj   = (const float*)d_in[1];
    const float* out_proj  = (const float*)d_in[2];
    const float* conv_w_a  = (const float*)d_in[3];
    const float* conv_b_a  = (const float*)d_in[4];
    const float* conv_w_b  = (const float*)d_in[5];
    const float* conv_b_b  = (const float*)d_in[6];
    const float* xproj_a   = (const float*)d_in[7];
    const float* xproj_b   = (const float*)d_in[8];
    const float* dtproj_a  = (const float*)d_in[9];
    const float* dtproj_b  = (const float*)d_in[10];
    const float* dtbias_a  = (const float*)d_in[11];
    const float* dtbias_b  = (const float*)d_in[12];
    const float* A_a_log   = (const float*)d_in[13];
    const float* A_b_log   = (const float*)d_in[14];
    const float* D_a       = (const float*)d_in[15];
    const float* D_b       = (const float*)d_in[16];
    float* out             = (float*)d_out;

    __nv_bfloat16* hidh  = sym_addr<__nv_bfloat16>(g_hidh);
    __nv_bfloat16* hidl  = sym_addr<__nv_bfloat16>(g_hidl);
    __nv_bfloat16* inph  = sym_addr<__nv_bfloat16>(g_inph);
    __nv_bfloat16* inpl  = sym_addr<__nv_bfloat16>(g_inpl);
    __nv_bfloat16* outph = sym_addr<__nv_bfloat16>(g_outph);
    __nv_bfloat16* outpl = sym_addr<__nv_bfloat16>(g_outpl);
    __nv_bfloat16* xpah  = sym_addr<__nv_bfloat16>(g_xpah);
    __nv_bfloat16* xpal  = sym_addr<__nv_bfloat16>(g_xpal);
    __nv_bfloat16* xpbh  = sym_addr<__nv_bfloat16>(g_xpbh);
    __nv_bfloat16* xpbl  = sym_addr<__nv_bfloat16>(g_xpbl);
    __nv_bfloat16* dtpah = sym_addr<__nv_bfloat16>(g_dtpah);
    __nv_bfloat16* dtpal = sym_addr<__nv_bfloat16>(g_dtpal);
    __nv_bfloat16* dtpbh = sym_addr<__nv_bfloat16>(g_dtpbh);
    __nv_bfloat16* dtpbl = sym_addr<__nv_bfloat16>(g_dtpbl);
    float*    xz    = sym_addr<float>(g_xz);
    __nv_bfloat16* xcah = sym_addr<__nv_bfloat16>(g_xcah);
    __nv_bfloat16* xcal = sym_addr<__nv_bfloat16>(g_xcal);
    __nv_bfloat16* xcbh = sym_addr<__nv_bfloat16>(g_xcbh);
    __nv_bfloat16* xcbl = sym_addr<__nv_bfloat16>(g_xcbl);
    uint32_t* xca_p = sym_addr<uint32_t>(g_xca_p);
    uint32_t* xcb_p = sym_addr<uint32_t>(g_xcb_p);
    __nv_bfloat16* dtinah = sym_addr<__nv_bfloat16>(g_dtinah);
    __nv_bfloat16* dtinal = sym_addr<__nv_bfloat16>(g_dtinal);
    __nv_bfloat16* dtinbh = sym_addr<__nv_bfloat16>(g_dtinbh);
    __nv_bfloat16* dtinbl = sym_addr<__nv_bfloat16>(g_dtinbl);
    float*    bca   = sym_addr<float>(g_bca);
    float*    bcb   = sym_addr<float>(g_bcb);
    uint32_t* da_p  = sym_addr<uint32_t>(g_da_p);
    uint32_t* db_p  = sym_addr<uint32_t>(g_db_p);
    float*    ya    = sym_addr<float>(g_ya);
    float*    yb    = sym_addr<float>(g_yb);
    __nv_bfloat16* yph = sym_addr<__nv_bfloat16>(g_yph);
    __nv_bfloat16* ypl = sym_addr<__nv_bfloat16>(g_ypl);

    set_gemm_attrs(gemm_cp<0,true,false>,  SMEM_T);
    set_gemm_attrs(gemm_cp<2,false,false>, SMEM_F);
    set_gemm_attrs(gemm_cp<1,false,false>, SMEM_F);
    set_gemm_attrs(gemm_cp<0,false,true>,  SMEM_F);

    // 0) split all weights + hidden into hi/lo planes
    {
        Seg s0{hidden,   hidh,  hidl,  (long)NTOT*DMODEL};
        Seg s1{in_proj,  inph,  inpl,  (long)2*DINNER*DMODEL};
        Seg s2{out_proj, outph, outpl, (long)DMODEL*DINNER};
        Seg s3{xproj_a,  xpah,  xpal,  (long)EPROJ*DINNER};
        Seg s4{xproj_b,  xpbh,  xpbl,  (long)EPROJ*DINNER};
        Seg s5{dtproj_a, dtpah, dtpal, (long)DINNER*DTRANK};
        Seg s6{dtproj_b, dtpbh, dtpbl, (long)DINNER*DTRANK};
        long total = s0.c+s1.c+s2.c+s3.c+s4.c+s5.c+s6.c;
        int blocks = (int)((total/4 + 255) / 256);
        split_multi<<<blocks, 256>>>(s0, s1, s2, s3, s4, s5, s6);
    }

    // 1) xz = in_proj(3072x768) @ hidden^T(768x8192), fp32 out (TB=true)
    {
        GArgs ga{inph, inpl, hidh, hidl, xz, nullptr, nullptr, nullptr, nullptr};
        dim3 grid(NTOT/128, (2*DINNER)/128, 1);
        gemm_cp<0,true,false><<<grid, 256, SMEM_T>>>(
            ga, ga, 2*DINNER, NTOT, DMODEL, DMODEL, DMODEL, NTOT);
    }

    // 2) conv + SiLU, both branches -> planes + packed
    {
        long total = (long)DINNER*NTOT/4;
        conv_silu_both<<<(int)(total/256), 256>>>(xz, conv_w_a, conv_b_a,
            conv_w_b, conv_b_b, xcah, xcal, xcbh, xcbl, xca_p, xcb_p);
    }

    // 3) x_proj both branches: dt rows -> planes, B/C -> interleaved fp32
    {
        GArgs a{xpah, xpal, xcah, xcal, bca, nullptr, dtinah, dtinal, nullptr};
        GArgs b{xpbh, xpbl, xcbh, xcbl, bcb, nullptr, dtinbh, dtinbl, nullptr};
        dim3 grid(NTOT/128, 1, 2);
        gemm_cp<2,false,false><<<grid, 256, SMEM_F>>>(
            a, b, EPROJ, NTOT, DINNER, DINNER, NTOT, NTOT);
    }

    // 4) delta = softplus(dtproj @ dtin + bias) -> packed (scan format)
    {
        GArgs a{dtpah, dtpal, dtinah, dtinal, nullptr, da_p, nullptr, nullptr, dtbias_a};
        GArgs b{dtpbh, dtpbl, dtinbh, dtinbl, nullptr, db_p, nullptr, nullptr, dtbias_b};
        dim3 grid(NTOT/128, DINNER/128, 2);
        gemm_cp<1,false,false><<<grid, 256, SMEM_F>>>(
            a, b, DINNER, NTOT, DTRANK, DTRANK, NTOT, NTOT);
    }

    // 5) both scans in one launch
    {
        ScanArgs sa{xca_p, da_p, bca, A_a_log, D_a, ya};
        ScanArgs sb{xcb_p, db_p, bcb, A_b_log, D_b, yb};
        int warps  = 2 * BB * (DINNER/2);
        int blocks = warps / 8;
        scan_both<<<blocks, 256>>>(sa, sb);
    }

    // 6) combine + gate -> planes
    {
        long total = (long)DINNER*NTOT/4;
        combine_kernel<<<(int)((total + 255)/256), 256>>>(ya, yb, xz, yph, ypl);
    }

    // 7) out^T: out_proj(768x1536) @ y(1536x8192), stored C[n][o]
    {
        GArgs ga{outph, outpl, yph, ypl, out, nullptr, nullptr, nullptr, nullptr};
        dim3 grid(NTOT/128, DMODEL/128, 1);
        gemm_cp<0,false,true><<<grid, 256, SMEM_F>>>(
            ga, ga, DMODEL, NTOT, DINNER, DINNER, NTOT, DMODEL);
    }
}

// round 9
// speedup vs baseline: 1.0805x; 1.0805x over previous
#include <cuda_runtime.h>
#include <cuda_bf16.h>
#include <cstdint>

// ---------------------------------------------------------------------------
// Problem constants
// ---------------------------------------------------------------------------
#define BB      2
#define LL      4096
#define DMODEL  768
#define DSTATE  16
#define DCONV   4
#define DINNER  1536
#define DTRANK  48
#define NTOT    (BB*LL)              // 8192
#define EPROJ   (DTRANK + 2*DSTATE)  // 80

// GEMM smem geometry (2-stage double buffer -> 2 blocks/SM resident)
#define PITCH_A   48                  // bytes/row, A & B(TB=true) smem (16 bf16 + pad)
#define PITCH_BF  272                 // bytes/row, B(TB=false) smem (128 bf16 + pad)
#define SLOT_A    (128*PITCH_A)       // 6144 per plane
#define SLOT_BF   (16*PITCH_BF)       // 4352 per plane
#define STAGE_T   (2*SLOT_A + 2*SLOT_A)    // 24576 (TB=true)
#define STAGE_F   (2*SLOT_A + 2*SLOT_BF)   // 20992 (TB=false)
#define SMEM_T    (2*STAGE_T)              // 49152
#define SMEM_F    (2*STAGE_F)              // 41984

// ---------------------------------------------------------------------------
// Scratch — GEMM operands as hi/lo bf16 planes; scan-facing data packed
// ---------------------------------------------------------------------------
__device__ __nv_bfloat16 g_hidh [NTOT*DMODEL],     g_hidl [NTOT*DMODEL];
__device__ __nv_bfloat16 g_inph [2*DINNER*DMODEL], g_inpl [2*DINNER*DMODEL];
__device__ __nv_bfloat16 g_outph[DMODEL*DINNER],   g_outpl[DMODEL*DINNER];
__device__ __nv_bfloat16 g_xpah [EPROJ*DINNER],    g_xpal [EPROJ*DINNER];
__device__ __nv_bfloat16 g_xpbh [EPROJ*DINNER],    g_xpbl [EPROJ*DINNER];
__device__ __nv_bfloat16 g_dtpah[DINNER*DTRANK],   g_dtpal[DINNER*DTRANK];
__device__ __nv_bfloat16 g_dtpbh[DINNER*DTRANK],   g_dtpbl[DINNER*DTRANK];

__device__ float         g_xz   [2*DINNER*NTOT];   // in_proj out fp32 (x | z)
__device__ __nv_bfloat16 g_xcah [DINNER*NTOT], g_xcal[DINNER*NTOT];  // GEMM3 B
__device__ __nv_bfloat16 g_xcbh [DINNER*NTOT], g_xcbl[DINNER*NTOT];
__device__ uint32_t      g_xca_p[DINNER*NTOT];     // scan u, packed lo<<16|hi
__device__ uint32_t      g_xcb_p[DINNER*NTOT];
__device__ __nv_bfloat16 g_dtinah[DTRANK*NTOT], g_dtinal[DTRANK*NTOT];
__device__ __nv_bfloat16 g_dtinbh[DTRANK*NTOT], g_dtinbl[DTRANK*NTOT];
__device__ float         g_bca  [2*DSTATE*NTOT];   // interleaved {B,C} fp32
__device__ float         g_bcb  [2*DSTATE*NTOT];
__device__ uint32_t      g_da_p [DINNER*NTOT];     // delta packed (scan only)
__device__ uint32_t      g_db_p [DINNER*NTOT];
__device__ float         g_ya   [DINNER*NTOT];
__device__ float         g_yb   [DINNER*NTOT];
__device__ __nv_bfloat16 g_yph  [DINNER*NTOT], g_ypl[DINNER*NTOT];

// ---------------------------------------------------------------------------
// Helpers
// ---------------------------------------------------------------------------
__device__ __forceinline__ float softplus_f(float x) {
    return (x > 20.f) ? x : log1pf(__expf(x));
}
__device__ __forceinline__ float silu_f(float x) {
    return x / (1.f + __expf(-x));
}
__device__ __forceinline__ void split_hl(float x, __nv_bfloat16& h, __nv_bfloat16& l) {
    h = __float2bfloat16(x);
    l = __float2bfloat16(x - __bfloat162float(h));
}
__device__ __forceinline__ uint32_t bfpack(__nv_bfloat16 a, __nv_bfloat16 b) {
    return ((uint32_t)__bfloat16_as_ushort(b) << 16) | (uint32_t)__bfloat16_as_ushort(a);
}
__device__ __forceinline__ uint32_t pack_bf2(float x) {
    __nv_bfloat16 h, l;
    split_hl(x, h, l);
    return ((uint32_t)__bfloat16_as_ushort(l) << 16) | (uint32_t)__bfloat16_as_ushort(h);
}
__device__ __forceinline__ float unpack_bf2(uint32_t w) {
    return __bfloat162float(__ushort_as_bfloat16((unsigned short)(w & 0xffffu))) +
           __bfloat162float(__ushort_as_bfloat16((unsigned short)(w >> 16)));
}
__device__ __forceinline__ void mma_bf16(float c[4], const uint32_t a[4], const uint32_t b[2]) {
    asm volatile(
        "mma.sync.aligned.m16n8k16.row.col.f32.bf16.bf16.f32 "
        "{%0,%1,%2,%3}, {%4,%5,%6,%7}, {%8,%9}, {%0,%1,%2,%3};"
        : "+f"(c[0]), "+f"(c[1]), "+f"(c[2]), "+f"(c[3])
        : "r"(a[0]), "r"(a[1]), "r"(a[2]), "r"(a[3]), "r"(b[0]), "r"(b[1]));
}
__device__ __forceinline__ uint32_t smem_u32(const void* p) {
    uint32_t a;
    asm("{ .reg .u64 t; cvta.to.shared.u64 t, %1; cvt.u32.u64 %0, t; }"
        : "=r"(a) : "l"(p));
    return a;
}
__device__ __forceinline__ void ldsm_x4(uint32_t* r, uint32_t a) {
    asm volatile("ldmatrix.sync.aligned.m8n8.x4.shared.b16 {%0,%1,%2,%3}, [%4];"
                 : "=r"(r[0]), "=r"(r[1]), "=r"(r[2]), "=r"(r[3]) : "r"(a));
}
__device__ __forceinline__ void ldsm_x4_t(uint32_t* r, uint32_t a) {
    asm volatile("ldmatrix.sync.aligned.m8n8.x4.trans.shared.b16 {%0,%1,%2,%3}, [%4];"
                 : "=r"(r[0]), "=r"(r[1]), "=r"(r[2]), "=r"(r[3]) : "r"(a));
}
__device__ __forceinline__ void cp16(uint32_t dst, const void* src) {
    asm volatile("cp.async.ca.shared.global [%0], [%1], 16;" :: "r"(dst), "l"(src));
}
#define CP_COMMIT() asm volatile("cp.async.commit_group;" ::: "memory")
#define CP_WAIT1()  asm volatile("cp.async.wait_group 1;" ::: "memory")

// ---------------------------------------------------------------------------
// bf16 3-pass GEMM, cp.async + ldmatrix, hi/lo plane operands.
//   EPI 0: fp32 C (CT: C[n][m]).
//   EPI 1: softplus(acc+bias[m]) -> packed C2 (scan format).
//   EPI 2: rows<48 -> planes Ch/Cl ; rows 48..79 -> interleaved {B,C} fp32 C.
// 2-stage cp.async double buffer (<=49KB/block -> 2 blocks/SM resident).
// ---------------------------------------------------------------------------
struct GArgs {
    const __nv_bfloat16 *Ah, *Al, *Bh, *Bl;
    float* C;
    uint32_t* C2;
    __nv_bfloat16 *Ch, *Cl;
    const float* bias;
};

template<int EPI, bool TB, bool CT>
__global__ __launch_bounds__(256, 2)
void gemm_cp(GArgs g0, GArgs g1, int M, int N, int K,
             int lda, int ldb, int ldc)
{
    constexpr int STAGE = TB ? STAGE_T : STAGE_F;
    extern __shared__ __align__(16) char smem[];
    const GArgs ga = blockIdx.z ? g1 : g0;

    const int tid  = threadIdx.x;
    const int w    = tid >> 5;
    const int wm   = w >> 2;
    const int wn   = w & 3;
    const int lane = tid & 31;
    const int gq   = lane >> 2;
    const int t    = lane & 3;
    const int l7   = lane & 7;
    const int mg   = lane >> 3;
    const int m0   = blockIdx.y * 128;
    const int n0   = blockIdx.x * 128;
    const uint32_t sbase = smem_u32(smem);

    const uint32_t aoff =
        (uint32_t)((wm*64 + l7 + ((mg & 1) << 3)) * PITCH_A + ((mg >> 1) << 4));
    uint32_t boff;
    if (!TB) boff = (uint32_t)((l7 + ((mg & 1) << 3)) * PITCH_BF
                               + (wn*32 + ((mg >> 1) << 3)) * 2);
    else     boff = (uint32_t)((wn*32 + l7 + ((mg >> 1) << 3)) * PITCH_A
                               + ((mg & 1) << 4));

    float acc[4][4][4];
#pragma unroll
    for (int i = 0; i < 4; ++i)
#pragma unroll
        for (int j = 0; j < 4; ++j)
#pragma unroll
            for (int c = 0; c < 4; ++c) acc[i][j][c] = 0.f;

    auto issue = [&](int st, int k0) {
        uint32_t sb = sbase + st*STAGE;
#pragma unroll
        for (int p = 0; p < 2; ++p) {
            int c = tid + p*256;
            int plane = c >> 8, row = (c >> 1) & 127, half = c & 1;
            int gm = m0 + row; if (gm > M-1) gm = M-1;
            const __nv_bfloat16* src =
                (plane ? ga.Al : ga.Ah) + (long)gm*lda + k0 + half*8;
            cp16(sb + plane*SLOT_A + row*PITCH_A + half*16, src);
        }
        uint32_t bb = sb + 2*SLOT_A;
        if (!TB) {
#pragma unroll
            for (int p = 0; p < 2; ++p) {
                int c = tid + p*256;
                int plane = c >> 8, row = (c >> 4) & 15, seg = c & 15;
                const __nv_bfloat16* src =
                    (plane ? ga.Bl : ga.Bh) + (long)(k0 + row)*ldb + n0 + seg*8;
                cp16(bb + plane*SLOT_BF + row*PITCH_BF + seg*16, src);
            }
        } else {
#pragma unroll
            for (int p = 0; p < 2; ++p) {
                int c = tid + p*256;
                int plane = c >> 8, row = (c >> 1) & 127, half = c & 1;
                const __nv_bfloat16* src =
                    (plane ? ga.Bl : ga.Bh) + (long)(n0 + row)*ldb + k0 + half*8;
                cp16(bb + plane*SLOT_A + row*PITCH_A + half*16, src);
            }
        }
    };

    const int iters = K / 16;
    issue(0, 0);  CP_COMMIT();
    issue(1, 16); CP_COMMIT();

    for (int it = 0; it < iters; ++it) {
        CP_WAIT1();
        __syncthreads();

        const uint32_t st = sbase + (it & 1)*STAGE;
        const uint32_t bb = st + 2*SLOT_A + boff;

        uint32_t bh[4][2], bl[4][2];
        if (!TB) {
            uint32_t r[4];
            ldsm_x4_t(r, bb);
            bh[0][0]=r[0]; bh[0][1]=r[1]; bh[1][0]=r[2]; bh[1][1]=r[3];
            ldsm_x4_t(r, bb + 32);
            bh[2][0]=r[0]; bh[2][1]=r[1]; bh[3][0]=r[2]; bh[3][1]=r[3];
            ldsm_x4_t(r, bb + SLOT_BF);
            bl[0][0]=r[0]; bl[0][1]=r[1]; bl[1][0]=r[2]; bl[1][1]=r[3];
            ldsm_x4_t(r, bb + SLOT_BF + 32);
            bl[2][0]=r[0]; bl[2][1]=r[1]; bl[3][0]=r[2]; bl[3][1]=r[3];
        } else {
            uint32_t r[4];
            ldsm_x4(r, bb);
            bh[0][0]=r[0]; bh[0][1]=r[1]; bh[1][0]=r[2]; bh[1][1]=r[3];
            ldsm_x4(r, bb + 16*PITCH_A);
            bh[2][0]=r[0]; bh[2][1]=r[1]; bh[3][0]=r[2]; bh[3][1]=r[3];
            ldsm_x4(r, bb + SLOT_A);
            bl[0][0]=r[0]; bl[0][1]=r[1]; bl[1][0]=r[2]; bl[1][1]=r[3];
            ldsm_x4(r, bb + SLOT_A + 16*PITCH_A);
            bl[2][0]=r[0]; bl[2][1]=r[1]; bl[3][0]=r[2]; bl[3][1]=r[3];
        }

#pragma unroll
        for (int mt = 0; mt < 4; ++mt) {
            uint32_t ah[4], al[4];
            ldsm_x4(ah, st + aoff + mt*16*PITCH_A);
            ldsm_x4(al, st + SLOT_A + aoff + mt*16*PITCH_A);
#pragma unroll
            for (int nt = 0; nt < 4; ++nt) mma_bf16(acc[mt][nt], ah, bh[nt]);
#pragma unroll
            for (int nt = 0; nt < 4; ++nt) mma_bf16(acc[mt][nt], ah, bl[nt]);
#pragma unroll
            for (int nt = 0; nt < 4; ++nt) mma_bf16(acc[mt][nt], al, bh[nt]);
        }

        __syncthreads();   // stage fully consumed before refill
        if (it + 2 < iters) { issue(it & 1, (it + 2) * 16); }
        CP_COMMIT();
    }

    // ---- epilogue ----
#pragma unroll
    for (int mt = 0; mt < 4; ++mt) {
#pragma unroll
        for (int nt = 0; nt < 4; ++nt) {
            int gm = m0 + wm*64 + mt*16 + gq;
            int gn = n0 + wn*32 + nt*8 + 2*t;
            float c0 = acc[mt][nt][0], c1 = acc[mt][nt][1];
            float c2 = acc[mt][nt][2], c3 = acc[mt][nt][3];
            if (EPI == 0) {
                if (!CT) {
                    if (gm < M) {
                        ga.C[(long)gm*ldc + gn]     = c0;
                        ga.C[(long)gm*ldc + gn + 1] = c1;
                    }
                    if (gm + 8 < M) {
                        ga.C[(long)(gm+8)*ldc + gn]     = c2;
                        ga.C[(long)(gm+8)*ldc + gn + 1] = c3;
                    }
                } else {
                    if (gm < M) {
                        ga.C[(long)gn*ldc + gm]       = c0;
                        ga.C[(long)(gn+1)*ldc + gm]   = c1;
                    }
                    if (gm + 8 < M) {
                        ga.C[(long)gn*ldc + gm + 8]     = c2;
                        ga.C[(long)(gn+1)*ldc + gm + 8] = c3;
                    }
                }
            } else if (EPI == 1) {
                if (gm < M) {
                    float b0 = ga.bias[gm];
                    ga.C2[(long)gm*ldc + gn]     = pack_bf2(softplus_f(c0 + b0));
                    ga.C2[(long)gm*ldc + gn + 1] = pack_bf2(softplus_f(c1 + b0));
                }
                if (gm + 8 < M) {
                    float b1 = ga.bias[gm + 8];
                    ga.C2[(long)(gm+8)*ldc + gn]     = pack_bf2(softplus_f(c2 + b1));
                    ga.C2[(long)(gm+8)*ldc + gn + 1] = pack_bf2(softplus_f(c3 + b1));
                }
            } else { // EPI 2
                if (gm < DTRANK) {
                    __nv_bfloat16 h0,l0,h1,l1;
                    split_hl(c0,h0,l0); split_hl(c1,h1,l1);
                    *(uint32_t*)(ga.Ch + (long)gm*ldc + gn) = bfpack(h0,h1);
                    *(uint32_t*)(ga.Cl + (long)gm*ldc + gn) = bfpack(l0,l1);
                } else if (gm < EPROJ) {
                    int r = gm - DTRANK, s = r & 15, wch = r >> 4;
                    ga.C[(((long)gn*16 + s) << 1) + wch]       = c0;
                    ga.C[(((long)(gn+1)*16 + s) << 1) + wch]   = c1;
                }
                if (gm + 8 < DTRANK) {
                    __nv_bfloat16 h2,l2,h3,l3;
                    split_hl(c2,h2,l2); split_hl(c3,h3,l3);
                    *(uint32_t*)(ga.Ch + (long)(gm+8)*ldc + gn) = bfpack(h2,h3);
                    *(uint32_t*)(ga.Cl + (long)(gm+8)*ldc + gn) = bfpack(l2,l3);
                } else if (gm + 8 < EPROJ) {
                    int r = gm + 8 - DTRANK, s = r & 15, wch = r >> 4;
                    ga.C[(((long)gn*16 + s) << 1) + wch]       = c2;
                    ga.C[(((long)(gn+1)*16 + s) << 1) + wch]   = c3;
                }
            }
        }
    }
}

// ---------------------------------------------------------------------------
// Split fp32 -> hi/lo bf16 planes, 7 segments fused
// ---------------------------------------------------------------------------
struct Seg { const float* s; __nv_bfloat16 *h, *l; long c; };

__global__ void split_multi(Seg s0, Seg s1, Seg s2, Seg s3, Seg s4, Seg s5, Seg s6)
{
    long q = ((long)blockIdx.x * blockDim.x + threadIdx.x) * 4;
    Seg sg;
    if      (q < s0.c) sg = s0;
    else if ((q -= s0.c) < s1.c) sg = s1;
    else if ((q -= s1.c) < s2.c) sg = s2;
    else if ((q -= s2.c) < s3.c) sg = s3;
    else if ((q -= s3.c) < s4.c) sg = s4;
    else if ((q -= s4.c) < s5.c) sg = s5;
    else if ((q -= s5.c) < s6.c) sg = s6;
    else return;
    float4 v = *(const float4*)(sg.s + q);
    __nv_bfloat16 h0,l0,h1,l1,h2,l2,h3,l3;
    split_hl(v.x,h0,l0); split_hl(v.y,h1,l1);
    split_hl(v.z,h2,l2); split_hl(v.w,h3,l3);
    *(uint2*)(sg.h + q) = make_uint2(bfpack(h0,h1), bfpack(h2,h3));
    *(uint2*)(sg.l + q) = make_uint2(bfpack(l0,l1), bfpack(l2,l3));
}

// ---------------------------------------------------------------------------
// Fused depthwise conv(w=4)+SiLU, both branches.
// Writes planes (GEMM3 operand) AND packed (scan operand).
// ---------------------------------------------------------------------------
__global__ __launch_bounds__(256)
void conv_silu_both(const float* __restrict__ x,
                    const float* __restrict__ wa, const float* __restrict__ ba,
                    const float* __restrict__ wb, const float* __restrict__ bb,
                    __nv_bfloat16* __restrict__ oah, __nv_bfloat16* __restrict__ oal,
                    __nv_bfloat16* __restrict__ obh, __nv_bfloat16* __restrict__ obl,
                    uint32_t* __restrict__ oap, uint32_t* __restrict__ obp)
{
    long q = (long)blockIdx.x * blockDim.x + threadIdx.x;   // 4 l per thread
    const long PERD = NTOT/4;
    int d  = (int)(q / PERD);
    int n4 = (int)(q % PERD);
    int n  = n4 * 4;
    int b  = n / LL;
    int l0 = n % LL;

    const float* xr = x + (long)d*NTOT + (long)b*LL;
    float4 prev = (l0 >= 4)      ? *(const float4*)(xr + l0 - 4) : make_float4(0,0,0,0);
    float4 cur  =                  *(const float4*)(xr + l0);
    float4 next = (l0 + 4 < LL)  ? *(const float4*)(xr + l0 + 4) : make_float4(0,0,0,0);

    float xa[8] = {prev.x, prev.y, prev.z, prev.w, cur.x, cur.y, cur.z, cur.w};
    float xb[8] = {cur.x, cur.y, cur.z, cur.w, next.x, next.y, next.z, next.w};

    float wav[4], wbv[4];
#pragma unroll
    for (int k = 0; k < 4; ++k) { wav[k] = wa[d*4+k]; wbv[k] = wb[d*4+k]; }
    float bav = ba[d], bbv = bb[d];

    __nv_bfloat16 ah[4], al[4], bh[4], bl[4];
#pragma unroll
    for (int j = 0; j < 4; ++j) {
        float sa = bav, sb = bbv;
#pragma unroll
        for (int k = 0; k < 4; ++k) {
            sa = fmaf(wav[k], xa[j + 1 + k], sa);
            sb = fmaf(wbv[k], xb[j + 3 - k], sb);
        }
        split_hl(silu_f(sa), ah[j], al[j]);
        split_hl(silu_f(sb), bh[j], bl[j]);
    }
    long off = (long)d*NTOT + n;
    *(uint2*)(oah + off) = make_uint2(bfpack(ah[0],ah[1]), bfpack(ah[2],ah[3]));
    *(uint2*)(oal + off) = make_uint2(bfpack(al[0],al[1]), bfpack(al[2],al[3]));
    *(uint2*)(obh + off) = make_uint2(bfpack(bh[0],bh[1]), bfpack(bh[2],bh[3]));
    *(uint2*)(obl + off) = make_uint2(bfpack(bl[0],bl[1]), bfpack(bl[2],bl[3]));
    uint4 pa, pb;
    pa.x = bfpack(ah[0], al[0]); pa.y = bfpack(ah[1], al[1]);
    pa.z = bfpack(ah[2], al[2]); pa.w = bfpack(ah[3], al[3]);
    pb.x = bfpack(bh[0], bl[0]); pb.y = bfpack(bh[1], bl[1]);
    pb.z = bfpack(bh[2], bl[2]); pb.w = bfpack(bh[3], bl[3]);
    *(uint4*)(oap + off) = pa;
    *(uint4*)(obp + off) = pb;
}

// ---------------------------------------------------------------------------
// Selective scan, packed u/delta, depth-1 prefetch. One warp = two units
// (d, d+768), same (branch,b). bc: float2 {B,C} at [(b*LL+l)*16 + state].
// ---------------------------------------------------------------------------
struct ScanArgs {
    const uint32_t *u, *dl;
    const float *bc, *Al, *Dv;
    float* y;
};

__global__ __launch_bounds__(256)
void scan_both(ScanArgs sa, ScanArgs sb)
{
    const int lane   = threadIdx.x & 31;
    const int lane16 = lane & 15;
    const int hh     = lane >> 4;
    int warpId = blockIdx.x * (blockDim.x >> 5) + (threadIdx.x >> 5);

    const int branch = warpId / (BB * (DINNER/2));
    int rem = warpId % (BB * (DINNER/2));
    const int b  = rem / (DINNER/2);
    const int dp = rem % (DINNER/2);
    const int d  = dp + hh * (DINNER/2);

    const ScanArgs& A_ = branch ? sb : sa;
    const bool fwd = (branch == 0);

    long base = (long)d*NTOT + (long)b*LL;
    const uint32_t* uR = A_.u  + base;
    const uint32_t* dR = A_.dl + base;
    const float2* bcR = (const float2*)A_.bc + ((long)b*LL)*16 + lane16;
    float* yR = A_.y + base;

    float A  = -__expf(A_.Al[d*DSTATE + lane16]);
    float Dd = A_.Dv[d];
    float hS = 0.f;

    int l0 = fwd ? 0 : LL - 4;
    uint4  u4 = *(const uint4*)(uR + l0);
    uint4  d4 = *(const uint4*)(dR + l0);
    float2 s0 = bcR[(long)(l0+0)*16];
    float2 s1 = bcR[(long)(l0+1)*16];
    float2 s2 = bcR[(long)(l0+2)*16];
    float2 s3 = bcR[(long)(l0+3)*16];

    for (int q = 0; q < LL/4; ++q) {
        int l0n = fwd ? (q+1)*4 : (LL - 8 - q*4);
        uint4 u4n = make_uint4(0,0,0,0), d4n = make_uint4(0,0,0,0);
        float2 t0 = make_float2(0,0), t1 = t0, t2 = t0, t3 = t0;
        if (q + 1 < LL/4) {
            u4n = *(const uint4*)(uR + l0n);
            d4n = *(const uint4*)(dR + l0n);
            t0 = bcR[(long)(l0n+0)*16];
            t1 = bcR[(long)(l0n+1)*16];
            t2 = bcR[(long)(l0n+2)*16];
            t3 = bcR[(long)(l0n+3)*16];
        }
        float uu[4] = {unpack_bf2(u4.x), unpack_bf2(u4.y), unpack_bf2(u4.z), unpack_bf2(u4.w)};
        float dd[4] = {unpack_bf2(d4.x), unpack_bf2(d4.y), unpack_bf2(d4.z), unpack_bf2(d4.w)};
        float Bv[4] = {s0.x, s1.x, s2.x, s3.x};
        float Cv[4] = {s0.y, s1.y, s2.y, s3.y};
        float yout[4];
#pragma unroll
        for (int j = 0; j < 4; ++j) {
            int jj = fwd ? j : 3 - j;
            float ut = uu[jj];
            float dt = dd[jj];
            float dA = __expf(dt * A);
            hS = fmaf(dA, hS, dt * ut * Bv[jj]);
            float p = hS * Cv[jj];
            p += __shfl_xor_sync(0xffffffffu, p, 1);
            p += __shfl_xor_sync(0xffffffffu, p, 2);
            p += __shfl_xor_sync(0xffffffffu, p, 4);
            p += __shfl_xor_sync(0xffffffffu, p, 8);
            yout[jj] = fmaf(ut, Dd, p);
        }
        if (lane16 == 0)
            *(float4*)(yR + l0) = make_float4(yout[0], yout[1], yout[2], yout[3]);
        u4 = u4n; d4 = d4n;
        s0 = t0; s1 = t1; s2 = t2; s3 = t3; l0 = l0n;
    }
}

// ---------------------------------------------------------------------------
// Combine: y = (ya + yb) * silu(z) -> planes (GEMM7 operand)
// ---------------------------------------------------------------------------
__global__ void combine_kernel(const float* __restrict__ ya,
                               const float* __restrict__ yb,
                               const float* __restrict__ xz,
                               __nv_bfloat16* __restrict__ yh,
                               __nv_bfloat16* __restrict__ yl)
{
    long q = ((long)blockIdx.x * blockDim.x + threadIdx.x) * 4;
    if (q >= (long)DINNER*NTOT) return;
    float4 a = *(const float4*)(ya + q);
    float4 b = *(const float4*)(yb + q);
    float4 z = *(const float4*)(xz + (long)DINNER*NTOT + q);
    __nv_bfloat16 h0,l0,h1,l1,h2,l2,h3,l3;
    split_hl((a.x + b.x) * silu_f(z.x), h0, l0);
    split_hl((a.y + b.y) * silu_f(z.y), h1, l1);
    split_hl((a.z + b.z) * silu_f(z.z), h2, l2);
    split_hl((a.w + b.w) * silu_f(z.w), h3, l3);
    *(uint2*)(yh + q) = make_uint2(bfpack(h0,h1), bfpack(h2,h3));
    *(uint2*)(yl + q) = make_uint2(bfpack(l0,l1), bfpack(l2,l3));
}

// ---------------------------------------------------------------------------
// Host launcher
// ---------------------------------------------------------------------------
template<typename T>
static T* sym_addr(const void* sym) {
    void* p = nullptr;
    cudaGetSymbolAddress(&p, sym);
    return (T*)p;
}

extern "C" void kernel_launch(void* const* d_in, const int* in_sizes, int n_in,
                              void* d_out, int out_size)
{
    const float* hidden    = (const float*)d_in[0];
    const float* in_proj   = (const float*)d_in[1];
    const float* out_proj  = (const float*)d_in[2];
    const float* conv_w_a  = (const float*)d_in[3];
    const float* conv_b_a  = (const float*)d_in[4];
    const float* conv_w_b  = (const float*)d_in[5];
    const float* conv_b_b  = (const float*)d_in[6];
    const float* xproj_a   = (const float*)d_in[7];
    const float* xproj_b   = (const float*)d_in[8];
    const float* dtproj_a  = (const float*)d_in[9];
    const float* dtproj_b  = (const float*)d_in[10];
    const float* dtbias_a  = (const float*)d_in[11];
    const float* dtbias_b  = (const float*)d_in[12];
    const float* A_a_log   = (const float*)d_in[13];
    const float* A_b_log   = (const float*)d_in[14];
    const float* D_a       = (const float*)d_in[15];
    const float* D_b       = (const float*)d_in[16];
    float* out             = (float*)d_out;

    __nv_bfloat16* hidh  = sym_addr<__nv_bfloat16>(g_hidh);
    __nv_bfloat16* hidl  = sym_addr<__nv_bfloat16>(g_hidl);
    __nv_bfloat16* inph  = sym_addr<__nv_bfloat16>(g_inph);
    __nv_bfloat16* inpl  = sym_addr<__nv_bfloat16>(g_inpl);
    __nv_bfloat16* outph = sym_addr<__nv_bfloat16>(g_outph);
    __nv_bfloat16* outpl = sym_addr<__nv_bfloat16>(g_outpl);
    __nv_bfloat16* xpah  = sym_addr<__nv_bfloat16>(g_xpah);
    __nv_bfloat16* xpal  = sym_addr<__nv_bfloat16>(g_xpal);
    __nv_bfloat16* xpbh  = sym_addr<__nv_bfloat16>(g_xpbh);
    __nv_bfloat16* xpbl  = sym_addr<__nv_bfloat16>(g_xpbl);
    __nv_bfloat16* dtpah = sym_addr<__nv_bfloat16>(g_dtpah);
    __nv_bfloat16* dtpal = sym_addr<__nv_bfloat16>(g_dtpal);
    __nv_bfloat16* dtpbh = sym_addr<__nv_bfloat16>(g_dtpbh);
    __nv_bfloat16* dtpbl = sym_addr<__nv_bfloat16>(g_dtpbl);
    float*    xz    = sym_addr<float>(g_xz);
    __nv_bfloat16* xcah = sym_addr<__nv_bfloat16>(g_xcah);
    __nv_bfloat16* xcal = sym_addr<__nv_bfloat16>(g_xcal);
    __nv_bfloat16* xcbh = sym_addr<__nv_bfloat16>(g_xcbh);
    __nv_bfloat16* xcbl = sym_addr<__nv_bfloat16>(g_xcbl);
    uint32_t* xca_p = sym_addr<uint32_t>(g_xca_p);
    uint32_t* xcb_p = sym_addr<uint32_t>(g_xcb_p);
    __nv_bfloat16* dtinah = sym_addr<__nv_bfloat16>(g_dtinah);
    __nv_bfloat16* dtinal = sym_addr<__nv_bfloat16>(g_dtinal);
    __nv_bfloat16* dtinbh = sym_addr<__nv_bfloat16>(g_dtinbh);
    __nv_bfloat16* dtinbl = sym_addr<__nv_bfloat16>(g_dtinbl);
    float*    bca   = sym_addr<float>(g_bca);
    float*    bcb   = sym_addr<float>(g_bcb);
    uint32_t* da_p  = sym_addr<uint32_t>(g_da_p);
    uint32_t* db_p  = sym_addr<uint32_t>(g_db_p);
    float*    ya    = sym_addr<float>(g_ya);
    float*    yb    = sym_addr<float>(g_yb);
    __nv_bfloat16* yph = sym_addr<__nv_bfloat16>(g_yph);
    __nv_bfloat16* ypl = sym_addr<__nv_bfloat16>(g_ypl);

    cudaFuncSetAttribute(gemm_cp<0,true,false>,
        cudaFuncAttributeMaxDynamicSharedMemorySize, SMEM_T);
    cudaFuncSetAttribute(gemm_cp<2,false,false>,
        cudaFuncAttributeMaxDynamicSharedMemorySize, SMEM_F);
    cudaFuncSetAttribute(gemm_cp<1,false,false>,
        cudaFuncAttributeMaxDynamicSharedMemorySize, SMEM_F);
    cudaFuncSetAttribute(gemm_cp<0,false,true>,
        cudaFuncAttributeMaxDynamicSharedMemorySize, SMEM_F);

    // 0) split all weights + hidden into hi/lo planes
    {
        Seg s0{hidden,   hidh,  hidl,  (long)NTOT*DMODEL};
        Seg s1{in_proj,  inph,  inpl,  (long)2*DINNER*DMODEL};
        Seg s2{out_proj, outph, outpl, (long)DMODEL*DINNER};
        Seg s3{xproj_a,  xpah,  xpal,  (long)EPROJ*DINNER};
        Seg s4{xproj_b,  xpbh,  xpbl,  (long)EPROJ*DINNER};
        Seg s5{dtproj_a, dtpah, dtpal, (long)DINNER*DTRANK};
        Seg s6{dtproj_b, dtpbh, dtpbl, (long)DINNER*DTRANK};
        long total = s0.c+s1.c+s2.c+s3.c+s4.c+s5.c+s6.c;
        int blocks = (int)((total/4 + 255) / 256);
        split_multi<<<blocks, 256>>>(s0, s1, s2, s3, s4, s5, s6);
    }

    // 1) xz = in_proj(3072x768) @ hidden^T(768x8192), fp32 out (TB=true)
    {
        GArgs ga{inph, inpl, hidh, hidl, xz, nullptr, nullptr, nullptr, nullptr};
        dim3 grid(NTOT/128, (2*DINNER)/128, 1);
        gemm_cp<0,true,false><<<grid, 256, SMEM_T>>>(
            ga, ga, 2*DINNER, NTOT, DMODEL, DMODEL, DMODEL, NTOT);
    }

    // 2) conv + SiLU, both branches -> planes + packed
    {
        long total = (long)DINNER*NTOT/4;
        conv_silu_both<<<(int)(total/256), 256>>>(xz, conv_w_a, conv_b_a,
            conv_w_b, conv_b_b, xcah, xcal, xcbh, xcbl, xca_p, xcb_p);
    }

    // 3) x_proj both branches: dt rows -> planes, B/C -> interleaved fp32
    {
        GArgs a{xpah, xpal, xcah, xcal, bca, nullptr, dtinah, dtinal, nullptr};
        GArgs b{xpbh, xpbl, xcbh, xcbl, bcb, nullptr, dtinbh, dtinbl, nullptr};
        dim3 grid(NTOT/128, 1, 2);
        gemm_cp<2,false,false><<<grid, 256, SMEM_F>>>(
            a, b, EPROJ, NTOT, DINNER, DINNER, NTOT, NTOT);
    }

    // 4) delta = softplus(dtproj @ dtin + bias) -> packed (scan format)
    {
        GArgs a{dtpah, dtpal, dtinah, dtinal, nullptr, da_p, nullptr, nullptr, dtbias_a};
        GArgs b{dtpbh, dtpbl, dtinbh, dtinbl, nullptr, db_p, nullptr, nullptr, dtbias_b};
        dim3 grid(NTOT/128, DINNER/128, 2);
        gemm_cp<1,false,false><<<grid, 256, SMEM_F>>>(
            a, b, DINNER, NTOT, DTRANK, DTRANK, NTOT, NTOT);
    }

    // 5) both scans in one launch
    {
        ScanArgs sa{xca_p, da_p, bca, A_a_log, D_a, ya};
        ScanArgs sb{xcb_p, db_p, bcb, A_b_log, D_b, yb};
        int warps  = 2 * BB * (DINNER/2);
        int blocks = warps / 8;
        scan_both<<<blocks, 256>>>(sa, sb);
    }

    // 6) combine + gate -> planes
    {
        long total = (long)DINNER*NTOT/4;
        combine_kernel<<<(int)((total + 255)/256), 256>>>(ya, yb, xz, yph, ypl);
    }

    // 7) out^T: out_proj(768x1536) @ y(1536x8192), stored C[n][o]
    {
        GArgs ga{outph, outpl, yph, ypl, out, nullptr, nullptr, nullptr, nullptr};
        dim3 grid(NTOT/128, DMODEL/128, 1);
        gemm_cp<0,false,true><<<grid, 256, SMEM_F>>>(
            ga, ga, DMODEL, NTOT, DINNER, DINNER, NTOT, DMODEL);
    }
}